// round 8
// baseline (speedup 1.0000x reference)
#include <cuda_runtime.h>
#include <cstdint>
#include <cstddef>

// ============================================================================
// Problem constants
// ============================================================================
static constexpr int BATCH  = 16384;
static constexpr int IN_DIM = 512;
static constexpr int UNITS  = 256;
static constexpr int NEXP   = 8;
static constexpr int NTASK  = 4;
static constexpr int NCOL   = UNITS * NEXP;   // 2048, n = u*8+e
static constexpr int GCOL   = NEXP * NTASK;   // 32,   g = e*4+t

// Fragment-block geometry (mma.m16n8k8)
static constexpr int MBLKS  = BATCH / 16;     // 1024
static constexpr int KBLKS  = IN_DIM / 8;     // 64
static constexpr int KBLK2S = IN_DIM / 16;    // 32
static constexpr int NBLKS  = NCOL / 8;       // 256

// Tiling
static constexpr int BM     = 64;             // 4 m_blks  (4096 CTAs -> ~1% tail)
static constexpr int BN     = 128;            // 16 n_blks (16 units x 8 experts)
static constexpr int KC     = 32;             // 4 k_blks / 2 k_blk2s
static constexpr int KSTEPS = IN_DIM / KC;    // 16
static constexpr int STAGES = 4;
static constexpr int NTHREADS = 256;          // 8 warps, 2(m) x 4(n), warp tile 32x32

// Shared memory (float4 units): stage = A(4*4*32) + B(16*2*32) = 1536 f4 = 24KB
static constexpr int A_STAGE_F4 = 4 * 4 * 32;     // 512
static constexpr int B_STAGE_F4 = 16 * 2 * 32;    // 1024
static constexpr int STAGE_F4   = A_STAGE_F4 + B_STAGE_F4;  // 1536
static constexpr int HDR_F4     = 32;             // be slice (128 floats)
static constexpr int SMEM_F4    = HDR_F4 + STAGES * STAGE_F4;
static constexpr int SMEM_BYTES = SMEM_F4 * 16;   // 98816 (x2 CTA = 193 KB)
static constexpr int C_LD       = BN + 4;         // 132 (staging 64*132*4 = 33.8 KB)

// ============================================================================
// Device scratch (no allocations allowed)
// ============================================================================
__device__ float  g_gates[BATCH * GCOL];                  // softmaxed gates [b][e*4+t]
__device__ float4 g_xA  [(size_t)MBLKS * KBLKS * 32];     // A fragments (32 MB)
__device__ float4 g_WeB [(size_t)NBLKS * KBLK2S * 32];    // B fragments ( 4 MB)

// ============================================================================
// Helpers
// ============================================================================
__device__ __forceinline__ uint32_t smem_u32(const void* p) {
    uint32_t a;
    asm("{ .reg .u64 t; cvta.to.shared.u64 t, %1; cvt.u32.u64 %0, t; }" : "=r"(a) : "l"(p));
    return a;
}
__device__ __forceinline__ float tf32_rn(float f) {
    uint32_t o; asm("cvt.rn.tf32.f32 %0, %1;" : "=r"(o) : "f"(f));
    return __uint_as_float(o);
}
__device__ __forceinline__ void cp_async16(uint32_t dst, const void* src) {
    asm volatile("cp.async.cg.shared.global [%0], [%1], 16;\n" :: "r"(dst), "l"(src));
}
#define CP_COMMIT()       asm volatile("cp.async.commit_group;\n" ::: "memory")
#define CP_WAIT_GROUP_2() asm volatile("cp.async.wait_group 2;\n" ::: "memory")

// D += A(16x8) * B(8x8), tf32 operands, f32 accum
__device__ __forceinline__ void mma_tf32(float* c, const float4& a, float b0, float b1) {
    asm volatile(
        "mma.sync.aligned.m16n8k8.row.col.f32.tf32.tf32.f32 "
        "{%0,%1,%2,%3}, {%4,%5,%6,%7}, {%8,%9}, {%0,%1,%2,%3};"
        : "+f"(c[0]), "+f"(c[1]), "+f"(c[2]), "+f"(c[3])
        : "r"(__float_as_uint(a.x)), "r"(__float_as_uint(a.y)),
          "r"(__float_as_uint(a.z)), "r"(__float_as_uint(a.w)),
          "r"(__float_as_uint(b0)),  "r"(__float_as_uint(b1)));
}

// ============================================================================
// prep We: tf32-round + pack into B-fragment order.
// ============================================================================
__global__ void __launch_bounds__(256)
prep_We_kernel(const float* __restrict__ We) {
    const int n_blk = blockIdx.x;
    const int t = threadIdx.x;
    #pragma unroll
    for (int i = 0; i < 4; i++) {
        int slot = t + i * 256;            // 1024 slots = 32 k2 x 32 lanes
        int k2   = slot >> 5;
        int lane = slot & 31;
        int gr = lane >> 2, tig = lane & 3;
        int n  = n_blk * 8 + gr;
        int kb = k2 * 16;
        float4 v;
        v.x = tf32_rn(__ldg(We + (size_t)(kb + tig)      * NCOL + n));
        v.y = tf32_rn(__ldg(We + (size_t)(kb + tig + 4)  * NCOL + n));
        v.z = tf32_rn(__ldg(We + (size_t)(kb + 8 + tig)  * NCOL + n));
        v.w = tf32_rn(__ldg(We + (size_t)(kb + 12 + tig) * NCOL + n));
        g_WeB[((size_t)n_blk * KBLK2S + k2) * 32 + lane] = v;
    }
}

// ============================================================================
// Gating kernel: softmaxed gates + x in A-fragment order.
// xs row stride padded to 516 -> conflict-free fragment-pack reads.
// ============================================================================
static constexpr int XS_LD = IN_DIM + 4;   // 516

__global__ void __launch_bounds__(512)
gate_kernel(const float4* __restrict__ x4, const float* __restrict__ Wg,
            const float* __restrict__ bg) {
    __shared__ float xs[16][XS_LD];
    __shared__ float ls[16][GCOL];
    const int tid = threadIdx.x;
    const int blk = blockIdx.x;            // m_blk
    const int b0  = blk * 16;

    // load + tf32-round into smem
    #pragma unroll
    for (int i = 0; i < 4; i++) {
        int idx = tid + i * 512;           // float4 index within 16x512 tile
        int rr = idx >> 7, c = idx & 127;
        float4 v = x4[(size_t)(b0 + rr) * (IN_DIM / 4) + c];
        v.x = tf32_rn(v.x); v.y = tf32_rn(v.y); v.z = tf32_rn(v.z); v.w = tf32_rn(v.w);
        *(float4*)&xs[rr][c * 4] = v;
    }
    __syncthreads();

    // write A fragments (2048 slots = 64 k_blk x 32 lanes)
    #pragma unroll
    for (int i = 0; i < 4; i++) {
        int slot = tid + i * 512;
        int k_blk = slot >> 5;
        int lane  = slot & 31;
        int gr = lane >> 2, tig = lane & 3;
        int kc = k_blk * 8;
        float4 v;
        v.x = xs[gr][kc + tig];
        v.y = xs[gr + 8][kc + tig];
        v.z = xs[gr][kc + tig + 4];
        v.w = xs[gr + 8][kc + tig + 4];
        g_xA[((size_t)blk * KBLKS + k_blk) * 32 + lane] = v;
    }

    // gate logits
    const int r = tid >> 5, g = tid & 31;
    float a0 = 0.f, a1 = 0.f, a2 = 0.f, a3 = 0.f;
    #pragma unroll 4
    for (int k = 0; k < IN_DIM; k += 4) {
        a0 += xs[r][k]     * Wg[(size_t)(k)     * GCOL + g];
        a1 += xs[r][k + 1] * Wg[(size_t)(k + 1) * GCOL + g];
        a2 += xs[r][k + 2] * Wg[(size_t)(k + 2) * GCOL + g];
        a3 += xs[r][k + 3] * Wg[(size_t)(k + 3) * GCOL + g];
    }
    ls[r][g] = (a0 + a1) + (a2 + a3) + bg[g];
    __syncthreads();

    if (tid < 64) {
        const int rr = tid >> 2, t = tid & 3;
        float v[NEXP], m = -3.4e38f;
        #pragma unroll
        for (int e = 0; e < NEXP; e++) { v[e] = ls[rr][e * 4 + t]; m = fmaxf(m, v[e]); }
        float den = 0.f;
        #pragma unroll
        for (int e = 0; e < NEXP; e++) { v[e] = expf(v[e] - m); den += v[e]; }
        const float inv = 1.f / den;
        #pragma unroll
        for (int e = 0; e < NEXP; e++)
            g_gates[(size_t)(b0 + rr) * GCOL + e * 4 + t] = v[e] * inv;
    }
}

// ============================================================================
// Main kernel: explicit mma.m16n8k8 tf32, BM=64 (fine-grained grid)
// ============================================================================
__global__ void __launch_bounds__(NTHREADS, 2)
moe_mma_kernel(const float* __restrict__ be, float* __restrict__ out) {
    extern __shared__ float4 smem4[];
    float*  sbe    = (float*)smem4;
    float4* stage0 = smem4 + HDR_F4;

    const int tid  = threadIdx.x;
    const int wid  = tid >> 5;
    const int lane = tid & 31;
    const int gr   = lane >> 2, tig = lane & 3;
    const int warp_m = wid >> 2;        // 0..1 -> rows warp_m*32
    const int warp_n = wid & 3;         // 0..3 -> cols warp_n*32

    const int n_tile = blockIdx.x & 15;
    const int b_tile = blockIdx.x >> 4;
    const int b0  = b_tile * BM;
    const int mb0 = b_tile * 4;         // global m_blk base
    const int nb0 = n_tile * 16;        // global n_blk base

    if (tid < BN) sbe[tid] = be[n_tile * BN + tid];

    float acc[2][4][4];                 // [mi][ni][frag]
    #pragma unroll
    for (int mi = 0; mi < 2; mi++)
        #pragma unroll
        for (int ni = 0; ni < 4; ni++)
            #pragma unroll
            for (int q = 0; q < 4; q++) acc[mi][ni][q] = 0.f;

    auto load_stage = [&](int slot, int kt) {
        float4* As = stage0 + slot * STAGE_F4;
        float4* Bs = As + A_STAGE_F4;
        const uint32_t aB = smem_u32(As);
        const uint32_t bB = smem_u32(Bs);
        // A: 512 chunks; c = (mb_l*4 + kb_l)*32 + lane -> 2 per thread
        #pragma unroll
        for (int i = 0; i < 2; i++) {
            int c = tid + i * 256;
            int mb = c >> 7, rem = c & 127;
            size_t g = ((size_t)(mb0 + mb) * KBLKS + (kt * 4 + (rem >> 5))) * 32 + (rem & 31);
            cp_async16(aB + (uint32_t)c * 16, g_xA + g);
        }
        // B: 1024 chunks; c = (nb_l*2 + k2_l)*32 + lane -> 4 per thread
        #pragma unroll
        for (int i = 0; i < 4; i++) {
            int c = tid + i * 256;
            int nb = c >> 6, rem = c & 63;
            size_t g = ((size_t)(nb0 + nb) * KBLK2S + (kt * 2 + (rem >> 5))) * 32 + (rem & 31);
            cp_async16(bB + (uint32_t)c * 16, g_WeB + g);
        }
    };

    auto compute_stage = [&](int slot) {
        const float4* As = stage0 + slot * STAGE_F4;
        const float4* Bs = As + A_STAGE_F4;
        #pragma unroll
        for (int k2 = 0; k2 < 2; k2++) {
            float4 Bv[4];
            #pragma unroll
            for (int ni = 0; ni < 4; ni++)
                Bv[ni] = Bs[((warp_n * 4 + ni) * 2 + k2) * 32 + lane];
            #pragma unroll
            for (int half = 0; half < 2; half++) {
                const int ks = k2 * 2 + half;
                float4 Av[2];
                #pragma unroll
                for (int mi = 0; mi < 2; mi++)
                    Av[mi] = As[((warp_m * 2 + mi) * 4 + ks) * 32 + lane];
                #pragma unroll
                for (int mi = 0; mi < 2; mi++)
                    #pragma unroll
                    for (int ni = 0; ni < 4; ni++) {
                        if (half == 0) mma_tf32(acc[mi][ni], Av[mi], Bv[ni].x, Bv[ni].y);
                        else           mma_tf32(acc[mi][ni], Av[mi], Bv[ni].z, Bv[ni].w);
                    }
            }
        }
    };

    // Prologue: fill 3 of 4 stages
    load_stage(0, 0); CP_COMMIT();
    load_stage(1, 1); CP_COMMIT();
    load_stage(2, 2); CP_COMMIT();

    // Main loop
    for (int kt = 0; kt < KSTEPS; kt++) {
        CP_WAIT_GROUP_2();
        __syncthreads();
        const int next = kt + 3;
        if (next < KSTEPS) load_stage(next & 3, next);
        CP_COMMIT();
        compute_stage(kt & 3);
    }

    // ------------------------------------------------------------------
    // Epilogue: stage C through smem, then bias+ReLU+gate combine
    // ------------------------------------------------------------------
    __syncthreads();
    float* Cs = (float*)stage0;   // 64 x 132 floats = 33.8 KB
    #pragma unroll
    for (int mi = 0; mi < 2; mi++) {
        #pragma unroll
        for (int ni = 0; ni < 4; ni++) {
            int row = warp_m * 32 + mi * 16 + gr;
            int col = warp_n * 32 + ni * 8 + 2 * tig;
            *(float2*)&Cs[row * C_LD + col]       = make_float2(acc[mi][ni][0], acc[mi][ni][1]);
            *(float2*)&Cs[(row + 8) * C_LD + col] = make_float2(acc[mi][ni][2], acc[mi][ni][3]);
        }
    }
    __syncthreads();

    const int r = tid >> 2;       // row in tile (0..63)
    const int h = tid & 3;        // column quarter (4 units each)
    const int b = b0 + r;

    float gate[GCOL];
    {
        const float4* gp = (const float4*)(g_gates + (size_t)b * GCOL);
        #pragma unroll
        for (int q = 0; q < 8; q++) ((float4*)gate)[q] = gp[q];
    }

    float accu[4][NTASK];
    #pragma unroll
    for (int u = 0; u < 4; u++)
        #pragma unroll
        for (int t = 0; t < NTASK; t++) accu[u][t] = 0.f;

    #pragma unroll
    for (int u = 0; u < 4; u++) {
        const int nl = h * 32 + u * 8;
        #pragma unroll
        for (int e = 0; e < NEXP; e++) {
            float v = Cs[r * C_LD + nl + e] + sbe[nl + e];
            v = fmaxf(v, 0.f);
            #pragma unroll
            for (int t = 0; t < NTASK; t++) accu[u][t] += v * gate[e * 4 + t];
        }
    }

    float* ob = out + (size_t)b * UNITS + n_tile * 16 + h * 4;
    #pragma unroll
    for (int t = 0; t < NTASK; t++) {
        float4 o = make_float4(accu[0][t], accu[1][t], accu[2][t], accu[3][t]);
        *(float4*)(ob + (size_t)t * BATCH * UNITS) = o;
    }
}

// ============================================================================
// Launch
// ============================================================================
extern "C" void kernel_launch(void* const* d_in, const int* in_sizes, int n_in,
                              void* d_out, int out_size) {
    const float* x  = (const float*)d_in[0];
    const float* We = (const float*)d_in[1];
    const float* be = (const float*)d_in[2];
    const float* Wg = (const float*)d_in[3];
    const float* bg = (const float*)d_in[4];
    float* out = (float*)d_out;

    cudaFuncSetAttribute(moe_mma_kernel, cudaFuncAttributeMaxDynamicSharedMemorySize, SMEM_BYTES);

    prep_We_kernel<<<NBLKS, 256>>>(We);
    gate_kernel<<<MBLKS, 512>>>((const float4*)x, Wg, bg);
    moe_mma_kernel<<<(BATCH / BM) * (NCOL / BN), NTHREADS, SMEM_BYTES>>>(be, out);
}

// round 10
// speedup vs baseline: 1.1231x; 1.1231x over previous
#include <cuda_runtime.h>
#include <cstdint>
#include <cstddef>

// ============================================================================
// Problem constants
// ============================================================================
static constexpr int BATCH  = 16384;
static constexpr int IN_DIM = 512;
static constexpr int UNITS  = 256;
static constexpr int NEXP   = 8;
static constexpr int NTASK  = 4;
static constexpr int NCOL   = UNITS * NEXP;   // 2048, n = u*8+e
static constexpr int GCOL   = NEXP * NTASK;   // 32,   g = e*4+t

// Fragment-block geometry (mma.m16n8k8)
static constexpr int MBLKS  = BATCH / 16;     // 1024
static constexpr int KBLKS  = IN_DIM / 8;     // 64
static constexpr int KBLK2S = IN_DIM / 16;    // 32
static constexpr int NBLKS  = NCOL / 8;       // 256

// Tiling: BM=64 (fine grid) with 4 warps of 32x64 (good issue mix)
static constexpr int BM     = 64;             // 4 m_blks -> 4096 CTAs
static constexpr int BN     = 128;            // 16 n_blks
static constexpr int KC     = 32;             // 4 k_blks / 2 k_blk2s
static constexpr int KSTEPS = IN_DIM / KC;    // 16
static constexpr int STAGES = 3;
static constexpr int NTHREADS = 128;          // 4 warps, 2(m) x 2(n), warp tile 32x64

// Shared memory (float4 units): stage = A(4*4*32) + B(16*2*32) = 1536 f4 = 24KB
static constexpr int A_STAGE_F4 = 4 * 4 * 32;     // 512
static constexpr int B_STAGE_F4 = 16 * 2 * 32;    // 1024
static constexpr int STAGE_F4   = A_STAGE_F4 + B_STAGE_F4;  // 1536
static constexpr int HDR_F4     = 32;             // be slice (128 floats)
static constexpr int SMEM_F4    = HDR_F4 + STAGES * STAGE_F4;
static constexpr int SMEM_BYTES = SMEM_F4 * 16;   // 74240 (x3 CTA = 223 KB)
static constexpr int C_LD       = BN + 4;         // 132 (staging 64*132*4 = 33.8 KB)

// ============================================================================
// Device scratch (no allocations allowed)
// ============================================================================
__device__ float  g_gates[BATCH * GCOL];                  // softmaxed gates [b][e*4+t]
__device__ float4 g_xA  [(size_t)MBLKS * KBLKS * 32];     // A fragments (32 MB)
__device__ float4 g_WeB [(size_t)NBLKS * KBLK2S * 32];    // B fragments ( 4 MB)

// ============================================================================
// Helpers
// ============================================================================
__device__ __forceinline__ uint32_t smem_u32(const void* p) {
    uint32_t a;
    asm("{ .reg .u64 t; cvta.to.shared.u64 t, %1; cvt.u32.u64 %0, t; }" : "=r"(a) : "l"(p));
    return a;
}
__device__ __forceinline__ float tf32_rn(float f) {
    uint32_t o; asm("cvt.rn.tf32.f32 %0, %1;" : "=r"(o) : "f"(f));
    return __uint_as_float(o);
}
__device__ __forceinline__ void cp_async16(uint32_t dst, const void* src) {
    asm volatile("cp.async.cg.shared.global [%0], [%1], 16;\n" :: "r"(dst), "l"(src));
}
#define CP_COMMIT()       asm volatile("cp.async.commit_group;\n" ::: "memory")
#define CP_WAIT_GROUP_1() asm volatile("cp.async.wait_group 1;\n" ::: "memory")

// D += A(16x8) * B(8x8), tf32 operands, f32 accum
__device__ __forceinline__ void mma_tf32(float* c, const float4& a, float b0, float b1) {
    asm volatile(
        "mma.sync.aligned.m16n8k8.row.col.f32.tf32.tf32.f32 "
        "{%0,%1,%2,%3}, {%4,%5,%6,%7}, {%8,%9}, {%0,%1,%2,%3};"
        : "+f"(c[0]), "+f"(c[1]), "+f"(c[2]), "+f"(c[3])
        : "r"(__float_as_uint(a.x)), "r"(__float_as_uint(a.y)),
          "r"(__float_as_uint(a.z)), "r"(__float_as_uint(a.w)),
          "r"(__float_as_uint(b0)),  "r"(__float_as_uint(b1)));
}

// ============================================================================
// Gating kernel: softmaxed gates + x in A-fragment order.
// Blocks 0..255 ALSO pack We into B-fragment order (merged prep_We).
// ============================================================================
static constexpr int XS_LD = IN_DIM + 4;   // 516 (conflict-free pack reads)

__global__ void __launch_bounds__(512)
gate_kernel(const float4* __restrict__ x4, const float* __restrict__ Wg,
            const float* __restrict__ bg, const float* __restrict__ We) {
    __shared__ float xs[16][XS_LD];
    __shared__ float ls[16][GCOL];
    const int tid = threadIdx.x;
    const int blk = blockIdx.x;            // m_blk
    const int b0  = blk * 16;

    // load + tf32-round into smem
    #pragma unroll
    for (int i = 0; i < 4; i++) {
        int idx = tid + i * 512;           // float4 index within 16x512 tile
        int rr = idx >> 7, c = idx & 127;
        float4 v = x4[(size_t)(b0 + rr) * (IN_DIM / 4) + c];
        v.x = tf32_rn(v.x); v.y = tf32_rn(v.y); v.z = tf32_rn(v.z); v.w = tf32_rn(v.w);
        *(float4*)&xs[rr][c * 4] = v;
    }
    __syncthreads();

    // write A fragments (2048 slots = 64 k_blk x 32 lanes)
    #pragma unroll
    for (int i = 0; i < 4; i++) {
        int slot = tid + i * 512;
        int k_blk = slot >> 5;
        int lane  = slot & 31;
        int gr = lane >> 2, tig = lane & 3;
        int kc = k_blk * 8;
        float4 v;
        v.x = xs[gr][kc + tig];
        v.y = xs[gr + 8][kc + tig];
        v.z = xs[gr][kc + tig + 4];
        v.w = xs[gr + 8][kc + tig + 4];
        g_xA[((size_t)blk * KBLKS + k_blk) * 32 + lane] = v;
    }

    // gate logits
    const int r = tid >> 5, g = tid & 31;
    float a0 = 0.f, a1 = 0.f, a2 = 0.f, a3 = 0.f;
    #pragma unroll 4
    for (int k = 0; k < IN_DIM; k += 4) {
        a0 += xs[r][k]     * Wg[(size_t)(k)     * GCOL + g];
        a1 += xs[r][k + 1] * Wg[(size_t)(k + 1) * GCOL + g];
        a2 += xs[r][k + 2] * Wg[(size_t)(k + 2) * GCOL + g];
        a3 += xs[r][k + 3] * Wg[(size_t)(k + 3) * GCOL + g];
    }
    ls[r][g] = (a0 + a1) + (a2 + a3) + bg[g];
    __syncthreads();

    if (tid < 64) {
        const int rr = tid >> 2, t = tid & 3;
        float v[NEXP], m = -3.4e38f;
        #pragma unroll
        for (int e = 0; e < NEXP; e++) { v[e] = ls[rr][e * 4 + t]; m = fmaxf(m, v[e]); }
        float den = 0.f;
        #pragma unroll
        for (int e = 0; e < NEXP; e++) { v[e] = expf(v[e] - m); den += v[e]; }
        const float inv = 1.f / den;
        #pragma unroll
        for (int e = 0; e < NEXP; e++)
            g_gates[(size_t)(b0 + rr) * GCOL + e * 4 + t] = v[e] * inv;
    }

    // merged prep_We: blocks 0..255 pack one n_blk each (independent work)
    if (blk < NBLKS) {
        const int n_blk = blk;
        #pragma unroll
        for (int i = 0; i < 2; i++) {
            int slot = tid + i * 512;          // 1024 slots = 32 k2 x 32 lanes
            int k2   = slot >> 5;
            int lane = slot & 31;
            int gr2 = lane >> 2, tig2 = lane & 3;
            int n  = n_blk * 8 + gr2;
            int kb = k2 * 16;
            float4 v;
            v.x = tf32_rn(__ldg(We + (size_t)(kb + tig2)      * NCOL + n));
            v.y = tf32_rn(__ldg(We + (size_t)(kb + tig2 + 4)  * NCOL + n));
            v.z = tf32_rn(__ldg(We + (size_t)(kb + 8 + tig2)  * NCOL + n));
            v.w = tf32_rn(__ldg(We + (size_t)(kb + 12 + tig2) * NCOL + n));
            g_WeB[((size_t)n_blk * KBLK2S + k2) * 32 + lane] = v;
        }
    }
}

// ============================================================================
// Main kernel: explicit mma.m16n8k8 tf32
// 128 threads, warp grid 2(m) x 2(n), warp tile 32x64, 3 CTAs/SM.
// ============================================================================
__global__ void __launch_bounds__(NTHREADS, 3)
moe_mma_kernel(const float* __restrict__ be, float* __restrict__ out) {
    extern __shared__ float4 smem4[];
    float*  sbe    = (float*)smem4;
    float4* stage0 = smem4 + HDR_F4;

    const int tid  = threadIdx.x;
    const int wid  = tid >> 5;
    const int lane = tid & 31;
    const int gr   = lane >> 2, tig = lane & 3;
    const int warp_m = wid >> 1;        // 0..1 -> rows warp_m*32
    const int warp_n = wid & 1;         // 0..1 -> cols warp_n*64

    const int n_tile = blockIdx.x & 15;
    const int b_tile = blockIdx.x >> 4;
    const int b0  = b_tile * BM;
    const int mb0 = b_tile * 4;         // global m_blk base
    const int nb0 = n_tile * 16;        // global n_blk base

    if (tid < BN) sbe[tid] = be[n_tile * BN + tid];

    float acc[2][8][4];                 // [mi][ni][frag]
    #pragma unroll
    for (int mi = 0; mi < 2; mi++)
        #pragma unroll
        for (int ni = 0; ni < 8; ni++)
            #pragma unroll
            for (int q = 0; q < 4; q++) acc[mi][ni][q] = 0.f;

    auto load_stage = [&](int slot, int kt) {
        float4* As = stage0 + slot * STAGE_F4;
        float4* Bs = As + A_STAGE_F4;
        const uint32_t aB = smem_u32(As);
        const uint32_t bB = smem_u32(Bs);
        // A: 512 chunks; c = (mb_l*4 + kb_l)*32 + lane -> 4 per thread
        #pragma unroll
        for (int i = 0; i < 4; i++) {
            int c = tid + i * 128;
            int mb = c >> 7, rem = c & 127;
            size_t g = ((size_t)(mb0 + mb) * KBLKS + (kt * 4 + (rem >> 5))) * 32 + (rem & 31);
            cp_async16(aB + (uint32_t)c * 16, g_xA + g);
        }
        // B: 1024 chunks; c = (nb_l*2 + k2_l)*32 + lane -> 8 per thread
        #pragma unroll
        for (int i = 0; i < 8; i++) {
            int c = tid + i * 128;
            int nb = c >> 6, rem = c & 63;
            size_t g = ((size_t)(nb0 + nb) * KBLK2S + (kt * 2 + (rem >> 5))) * 32 + (rem & 31);
            cp_async16(bB + (uint32_t)c * 16, g_WeB + g);
        }
    };

    auto compute_stage = [&](int slot) {
        const float4* As = stage0 + slot * STAGE_F4;
        const float4* Bs = As + A_STAGE_F4;
        #pragma unroll
        for (int k2 = 0; k2 < 2; k2++) {
            float4 Bv[8];
            #pragma unroll
            for (int ni = 0; ni < 8; ni++)
                Bv[ni] = Bs[((warp_n * 8 + ni) * 2 + k2) * 32 + lane];
            #pragma unroll
            for (int half = 0; half < 2; half++) {
                const int ks = k2 * 2 + half;
                float4 Av[2];
                #pragma unroll
                for (int mi = 0; mi < 2; mi++)
                    Av[mi] = As[((warp_m * 2 + mi) * 4 + ks) * 32 + lane];
                #pragma unroll
                for (int mi = 0; mi < 2; mi++)
                    #pragma unroll
                    for (int ni = 0; ni < 8; ni++) {
                        if (half == 0) mma_tf32(acc[mi][ni], Av[mi], Bv[ni].x, Bv[ni].y);
                        else           mma_tf32(acc[mi][ni], Av[mi], Bv[ni].z, Bv[ni].w);
                    }
            }
        }
    };

    // Prologue: fill 2 of 3 stages
    load_stage(0, 0); CP_COMMIT();
    load_stage(1, 1); CP_COMMIT();

    // Main loop
    for (int kt = 0; kt < KSTEPS; kt++) {
        CP_WAIT_GROUP_1();
        __syncthreads();
        const int next = kt + 2;
        if (next < KSTEPS) load_stage(next % STAGES, next);
        CP_COMMIT();
        compute_stage(kt % STAGES);
    }

    // ------------------------------------------------------------------
    // Epilogue: stage C through smem, then bias+ReLU+gate combine
    // ------------------------------------------------------------------
    __syncthreads();
    float* Cs = (float*)stage0;   // 64 x 132 floats = 33.8 KB
    #pragma unroll
    for (int mi = 0; mi < 2; mi++) {
        #pragma unroll
        for (int ni = 0; ni < 8; ni++) {
            int row = warp_m * 32 + mi * 16 + gr;
            int col = warp_n * 64 + ni * 8 + 2 * tig;
            *(float2*)&Cs[row * C_LD + col]       = make_float2(acc[mi][ni][0], acc[mi][ni][1]);
            *(float2*)&Cs[(row + 8) * C_LD + col] = make_float2(acc[mi][ni][2], acc[mi][ni][3]);
        }
    }
    __syncthreads();

    const int r = tid >> 1;       // row in tile (0..63)
    const int h = tid & 1;        // column half (8 units each)
    const int b = b0 + r;

    float gate[GCOL];
    {
        const float4* gp = (const float4*)(g_gates + (size_t)b * GCOL);
        #pragma unroll
        for (int q = 0; q < 8; q++) ((float4*)gate)[q] = gp[q];
    }

    float accu[8][NTASK];
    #pragma unroll
    for (int u = 0; u < 8; u++)
        #pragma unroll
        for (int t = 0; t < NTASK; t++) accu[u][t] = 0.f;

    #pragma unroll
    for (int u = 0; u < 8; u++) {
        const int nl = (h * 8 + u) * 8;
        #pragma unroll
        for (int e = 0; e < NEXP; e++) {
            float v = Cs[r * C_LD + nl + e] + sbe[nl + e];
            v = fmaxf(v, 0.f);
            #pragma unroll
            for (int t = 0; t < NTASK; t++) accu[u][t] += v * gate[e * 4 + t];
        }
    }

    float* ob = out + (size_t)b * UNITS + n_tile * 16 + h * 8;
    #pragma unroll
    for (int t = 0; t < NTASK; t++) {
        float4 o0 = make_float4(accu[0][t], accu[1][t], accu[2][t], accu[3][t]);
        float4 o1 = make_float4(accu[4][t], accu[5][t], accu[6][t], accu[7][t]);
        *(float4*)(ob + (size_t)t * BATCH * UNITS)     = o0;
        *(float4*)(ob + (size_t)t * BATCH * UNITS + 4) = o1;
    }
}

// ============================================================================
// Launch
// ============================================================================
extern "C" void kernel_launch(void* const* d_in, const int* in_sizes, int n_in,
                              void* d_out, int out_size) {
    const float* x  = (const float*)d_in[0];
    const float* We = (const float*)d_in[1];
    const float* be = (const float*)d_in[2];
    const float* Wg = (const float*)d_in[3];
    const float* bg = (const float*)d_in[4];
    float* out = (float*)d_out;

    cudaFuncSetAttribute(moe_mma_kernel, cudaFuncAttributeMaxDynamicSharedMemorySize, SMEM_BYTES);

    gate_kernel<<<MBLKS, 512>>>((const float4*)x, Wg, bg, We);
    moe_mma_kernel<<<(BATCH / BM) * (NCOL / BN), NTHREADS, SMEM_BYTES>>>(be, out);
}

// round 12
// speedup vs baseline: 1.2083x; 1.0759x over previous
#include <cuda_runtime.h>
#include <cstdint>
#include <cstddef>

// ============================================================================
// Problem constants
// ============================================================================
static constexpr int BATCH  = 16384;
static constexpr int IN_DIM = 512;
static constexpr int UNITS  = 256;
static constexpr int NEXP   = 8;
static constexpr int NTASK  = 4;
static constexpr int NCOL   = UNITS * NEXP;   // 2048, n = u*8+e
static constexpr int GCOL   = NEXP * NTASK;   // 32,   g = e*4+t

// Fragment-block geometry (mma.m16n8k8)
static constexpr int MBLKS  = BATCH / 16;     // 1024
static constexpr int KBLKS  = IN_DIM / 8;     // 64
static constexpr int KBLK2S = IN_DIM / 16;    // 32
static constexpr int NBLKS  = NCOL / 8;       // 256

// Tiling: 4 warps of 64x64 (max fragment reuse -> min L1 port traffic)
static constexpr int BM     = 128;            // 8 m_blks -> 2048 CTAs
static constexpr int BN     = 128;            // 16 n_blks
static constexpr int KC     = 32;             // 4 k_blks / 2 k_blk2s
static constexpr int KSTEPS = IN_DIM / KC;    // 16
static constexpr int STAGES = 3;
static constexpr int NTHREADS = 128;          // 4 warps, 2(m) x 2(n), warp tile 64x64

// Shared memory (float4 units): stage = A(8*4*32) + B(16*2*32) = 2048 f4 = 32KB
static constexpr int A_STAGE_F4 = 8 * 4 * 32;     // 1024
static constexpr int B_STAGE_F4 = 16 * 2 * 32;    // 1024
static constexpr int STAGE_F4   = A_STAGE_F4 + B_STAGE_F4;  // 2048
static constexpr int HDR_F4     = 32;             // be slice (128 floats)
static constexpr int SMEM_F4    = HDR_F4 + STAGES * STAGE_F4;
static constexpr int SMEM_BYTES = SMEM_F4 * 16;   // 98816 (x2 CTA = 193 KB)
static constexpr int C_LD       = BN + 4;         // 132 (staging 128*132*4 = 67.6 KB)

// ============================================================================
// Device scratch (no allocations allowed)
// ============================================================================
__device__ float  g_gates[BATCH * GCOL];                  // softmaxed gates [b][e*4+t]
__device__ float4 g_xA  [(size_t)MBLKS * KBLKS * 32];     // A fragments (32 MB)
__device__ float4 g_WeB [(size_t)NBLKS * KBLK2S * 32];    // B fragments ( 4 MB)

// ============================================================================
// Helpers
// ============================================================================
__device__ __forceinline__ uint32_t smem_u32(const void* p) {
    uint32_t a;
    asm("{ .reg .u64 t; cvta.to.shared.u64 t, %1; cvt.u32.u64 %0, t; }" : "=r"(a) : "l"(p));
    return a;
}
__device__ __forceinline__ float tf32_rn(float f) {
    uint32_t o; asm("cvt.rn.tf32.f32 %0, %1;" : "=r"(o) : "f"(f));
    return __uint_as_float(o);
}
__device__ __forceinline__ void cp_async16(uint32_t dst, const void* src) {
    asm volatile("cp.async.cg.shared.global [%0], [%1], 16;\n" :: "r"(dst), "l"(src));
}
#define CP_COMMIT()       asm volatile("cp.async.commit_group;\n" ::: "memory")
#define CP_WAIT_GROUP_1() asm volatile("cp.async.wait_group 1;\n" ::: "memory")

// D += A(16x8) * B(8x8), tf32 operands, f32 accum
__device__ __forceinline__ void mma_tf32(float* c, const float4& a, float b0, float b1) {
    asm volatile(
        "mma.sync.aligned.m16n8k8.row.col.f32.tf32.tf32.f32 "
        "{%0,%1,%2,%3}, {%4,%5,%6,%7}, {%8,%9}, {%0,%1,%2,%3};"
        : "+f"(c[0]), "+f"(c[1]), "+f"(c[2]), "+f"(c[3])
        : "r"(__float_as_uint(a.x)), "r"(__float_as_uint(a.y)),
          "r"(__float_as_uint(a.z)), "r"(__float_as_uint(a.w)),
          "r"(__float_as_uint(b0)),  "r"(__float_as_uint(b1)));
}

// ============================================================================
// prep We: tf32-round + pack into B-fragment order (separate launch)
// ============================================================================
__global__ void __launch_bounds__(256)
prep_We_kernel(const float* __restrict__ We) {
    const int n_blk = blockIdx.x;
    const int t = threadIdx.x;
    #pragma unroll
    for (int i = 0; i < 4; i++) {
        int slot = t + i * 256;            // 1024 slots = 32 k2 x 32 lanes
        int k2   = slot >> 5;
        int lane = slot & 31;
        int gr = lane >> 2, tig = lane & 3;
        int n  = n_blk * 8 + gr;
        int kb = k2 * 16;
        float4 v;
        v.x = tf32_rn(__ldg(We + (size_t)(kb + tig)      * NCOL + n));
        v.y = tf32_rn(__ldg(We + (size_t)(kb + tig + 4)  * NCOL + n));
        v.z = tf32_rn(__ldg(We + (size_t)(kb + 8 + tig)  * NCOL + n));
        v.w = tf32_rn(__ldg(We + (size_t)(kb + 12 + tig) * NCOL + n));
        g_WeB[((size_t)n_blk * KBLK2S + k2) * 32 + lane] = v;
    }
}

// ============================================================================
// Gating kernel: softmaxed gates + x in A-fragment order.
// ============================================================================
static constexpr int XS_LD = IN_DIM + 4;   // 516 (conflict-free pack reads)

__global__ void __launch_bounds__(512)
gate_kernel(const float4* __restrict__ x4, const float* __restrict__ Wg,
            const float* __restrict__ bg) {
    __shared__ float xs[16][XS_LD];
    __shared__ float ls[16][GCOL];
    const int tid = threadIdx.x;
    const int blk = blockIdx.x;            // m_blk
    const int b0  = blk * 16;

    // load + tf32-round into smem
    #pragma unroll
    for (int i = 0; i < 4; i++) {
        int idx = tid + i * 512;           // float4 index within 16x512 tile
        int rr = idx >> 7, c = idx & 127;
        float4 v = x4[(size_t)(b0 + rr) * (IN_DIM / 4) + c];
        v.x = tf32_rn(v.x); v.y = tf32_rn(v.y); v.z = tf32_rn(v.z); v.w = tf32_rn(v.w);
        *(float4*)&xs[rr][c * 4] = v;
    }
    __syncthreads();

    // write A fragments (2048 slots = 64 k_blk x 32 lanes)
    #pragma unroll
    for (int i = 0; i < 4; i++) {
        int slot = tid + i * 512;
        int k_blk = slot >> 5;
        int lane  = slot & 31;
        int gr = lane >> 2, tig = lane & 3;
        int kc = k_blk * 8;
        float4 v;
        v.x = xs[gr][kc + tig];
        v.y = xs[gr + 8][kc + tig];
        v.z = xs[gr][kc + tig + 4];
        v.w = xs[gr + 8][kc + tig + 4];
        g_xA[((size_t)blk * KBLKS + k_blk) * 32 + lane] = v;
    }

    // gate logits
    const int r = tid >> 5, g = tid & 31;
    float a0 = 0.f, a1 = 0.f, a2 = 0.f, a3 = 0.f;
    #pragma unroll 4
    for (int k = 0; k < IN_DIM; k += 4) {
        a0 += xs[r][k]     * Wg[(size_t)(k)     * GCOL + g];
        a1 += xs[r][k + 1] * Wg[(size_t)(k + 1) * GCOL + g];
        a2 += xs[r][k + 2] * Wg[(size_t)(k + 2) * GCOL + g];
        a3 += xs[r][k + 3] * Wg[(size_t)(k + 3) * GCOL + g];
    }
    ls[r][g] = (a0 + a1) + (a2 + a3) + bg[g];
    __syncthreads();

    if (tid < 64) {
        const int rr = tid >> 2, t = tid & 3;
        float v[NEXP], m = -3.4e38f;
        #pragma unroll
        for (int e = 0; e < NEXP; e++) { v[e] = ls[rr][e * 4 + t]; m = fmaxf(m, v[e]); }
        float den = 0.f;
        #pragma unroll
        for (int e = 0; e < NEXP; e++) { v[e] = expf(v[e] - m); den += v[e]; }
        const float inv = 1.f / den;
        #pragma unroll
        for (int e = 0; e < NEXP; e++)
            g_gates[(size_t)(b0 + rr) * GCOL + e * 4 + t] = v[e] * inv;
    }
}

// ============================================================================
// Main kernel: mma.m16n8k8 tf32, 64x64 warp tiles (min L1-port per MMA)
// 128 threads, warp grid 2(m) x 2(n), 2 CTAs/SM.
// ============================================================================
__global__ void __launch_bounds__(NTHREADS, 2)
moe_mma_kernel(const float* __restrict__ be, float* __restrict__ out) {
    extern __shared__ float4 smem4[];
    float*  sbe    = (float*)smem4;
    float4* stage0 = smem4 + HDR_F4;

    const int tid  = threadIdx.x;
    const int wid  = tid >> 5;
    const int lane = tid & 31;
    const int gr   = lane >> 2, tig = lane & 3;
    const int warp_m = wid >> 1;        // 0..1 -> rows warp_m*64
    const int warp_n = wid & 1;         // 0..1 -> cols warp_n*64

    const int n_tile = blockIdx.x & 15;
    const int b_tile = blockIdx.x >> 4;
    const int b0  = b_tile * BM;
    const int mb0 = b_tile * 8;         // global m_blk base
    const int nb0 = n_tile * 16;        // global n_blk base

    if (tid < BN) sbe[tid] = be[n_tile * BN + tid];

    float acc[4][8][4];                 // [mi][ni][frag] = 128 regs
    #pragma unroll
    for (int mi = 0; mi < 4; mi++)
        #pragma unroll
        for (int ni = 0; ni < 8; ni++)
            #pragma unroll
            for (int q = 0; q < 4; q++) acc[mi][ni][q] = 0.f;

    auto load_stage = [&](int slot, int kt) {
        float4* As = stage0 + slot * STAGE_F4;
        float4* Bs = As + A_STAGE_F4;
        const uint32_t aB = smem_u32(As);
        const uint32_t bB = smem_u32(Bs);
        // A: 1024 chunks; c = (mb_l*4 + kb_l)*32 + lane -> 8 per thread
        #pragma unroll
        for (int i = 0; i < 8; i++) {
            int c = tid + i * 128;
            int mb = c >> 7, rem = c & 127;
            size_t g = ((size_t)(mb0 + mb) * KBLKS + (kt * 4 + (rem >> 5))) * 32 + (rem & 31);
            cp_async16(aB + (uint32_t)c * 16, g_xA + g);
        }
        // B: 1024 chunks; c = (nb_l*2 + k2_l)*32 + lane -> 8 per thread
        #pragma unroll
        for (int i = 0; i < 8; i++) {
            int c = tid + i * 128;
            int nb = c >> 6, rem = c & 63;
            size_t g = ((size_t)(nb0 + nb) * KBLK2S + (kt * 2 + (rem >> 5))) * 32 + (rem & 31);
            cp_async16(bB + (uint32_t)c * 16, g_WeB + g);
        }
    };

    auto compute_stage = [&](int slot) {
        const float4* As = stage0 + slot * STAGE_F4;
        const float4* Bs = As + A_STAGE_F4;
        #pragma unroll
        for (int k2 = 0; k2 < 2; k2++) {
            float4 Bv[8];
            #pragma unroll
            for (int ni = 0; ni < 8; ni++)
                Bv[ni] = Bs[((warp_n * 8 + ni) * 2 + k2) * 32 + lane];
            #pragma unroll
            for (int half = 0; half < 2; half++) {
                const int ks = k2 * 2 + half;
                float4 Av[4];
                #pragma unroll
                for (int mi = 0; mi < 4; mi++)
                    Av[mi] = As[((warp_m * 4 + mi) * 4 + ks) * 32 + lane];
                #pragma unroll
                for (int mi = 0; mi < 4; mi++)
                    #pragma unroll
                    for (int ni = 0; ni < 8; ni++) {
                        if (half == 0) mma_tf32(acc[mi][ni], Av[mi], Bv[ni].x, Bv[ni].y);
                        else           mma_tf32(acc[mi][ni], Av[mi], Bv[ni].z, Bv[ni].w);
                    }
            }
        }
    };

    // Prologue: fill 2 of 3 stages
    load_stage(0, 0); CP_COMMIT();
    load_stage(1, 1); CP_COMMIT();

    // Main loop
    for (int kt = 0; kt < KSTEPS; kt++) {
        CP_WAIT_GROUP_1();
        __syncthreads();
        const int next = kt + 2;
        if (next < KSTEPS) load_stage(next % STAGES, next);
        CP_COMMIT();
        compute_stage(kt % STAGES);
    }

    // ------------------------------------------------------------------
    // Epilogue: stage C through smem, then bias+ReLU+gate combine
    // ------------------------------------------------------------------
    __syncthreads();
    float* Cs = (float*)stage0;   // 128 x 132 floats = 67.6 KB
    #pragma unroll
    for (int mi = 0; mi < 4; mi++) {
        #pragma unroll
        for (int ni = 0; ni < 8; ni++) {
            int row = warp_m * 64 + mi * 16 + gr;
            int col = warp_n * 64 + ni * 8 + 2 * tig;
            *(float2*)&Cs[row * C_LD + col]       = make_float2(acc[mi][ni][0], acc[mi][ni][1]);
            *(float2*)&Cs[(row + 8) * C_LD + col] = make_float2(acc[mi][ni][2], acc[mi][ni][3]);
        }
    }
    __syncthreads();

    const int r = tid;            // row in tile (0..127), one row per thread
    const int b = b0 + r;

    float gate[GCOL];
    {
        const float4* gp = (const float4*)(g_gates + (size_t)b * GCOL);
        #pragma unroll
        for (int q = 0; q < 8; q++) ((float4*)gate)[q] = gp[q];
    }

    float accu[16][NTASK];
    #pragma unroll
    for (int u = 0; u < 16; u++)
        #pragma unroll
        for (int t = 0; t < NTASK; t++) accu[u][t] = 0.f;

    #pragma unroll
    for (int u = 0; u < 16; u++) {
        const int nl = u * 8;
        #pragma unroll
        for (int e = 0; e < NEXP; e++) {
            float v = Cs[r * C_LD + nl + e] + sbe[nl + e];
            v = fmaxf(v, 0.f);
            #pragma unroll
            for (int t = 0; t < NTASK; t++) accu[u][t] += v * gate[e * 4 + t];
        }
    }

    float* ob = out + (size_t)b * UNITS + n_tile * 16;
    #pragma unroll
    for (int t = 0; t < NTASK; t++) {
        #pragma unroll
        for (int q = 0; q < 4; q++) {
            float4 o = make_float4(accu[q * 4 + 0][t], accu[q * 4 + 1][t],
                                   accu[q * 4 + 2][t], accu[q * 4 + 3][t]);
            *(float4*)(ob + (size_t)t * BATCH * UNITS + q * 4) = o;
        }
    }
}

// ============================================================================
// Launch
// ============================================================================
extern "C" void kernel_launch(void* const* d_in, const int* in_sizes, int n_in,
                              void* d_out, int out_size) {
    const float* x  = (const float*)d_in[0];
    const float* We = (const float*)d_in[1];
    const float* be = (const float*)d_in[2];
    const float* Wg = (const float*)d_in[3];
    const float* bg = (const float*)d_in[4];
    float* out = (float*)d_out;

    cudaFuncSetAttribute(moe_mma_kernel, cudaFuncAttributeMaxDynamicSharedMemorySize, SMEM_BYTES);

    prep_We_kernel<<<NBLKS, 256>>>(We);
    gate_kernel<<<MBLKS, 512>>>((const float4*)x, Wg, bg);
    moe_mma_kernel<<<(BATCH / BM) * (NCOL / BN), NTHREADS, SMEM_BYTES>>>(be, out);
}

// round 13
// speedup vs baseline: 1.4330x; 1.1859x over previous
#include <cuda_runtime.h>
#include <cstdint>
#include <cstddef>

// ============================================================================
// Problem constants
// ============================================================================
static constexpr int BATCH  = 16384;
static constexpr int IN_DIM = 512;
static constexpr int UNITS  = 256;
static constexpr int NEXP   = 8;
static constexpr int NTASK  = 4;
static constexpr int NCOL   = UNITS * NEXP;   // 2048, n = u*8+e
static constexpr int GCOL   = NEXP * NTASK;   // 32,   g = e*4+t

// Fragment-block geometry (mma.m16n8k8)
static constexpr int MBLKS  = BATCH / 16;     // 1024
static constexpr int KBLKS  = IN_DIM / 8;     // 64
static constexpr int KBLK2S = IN_DIM / 16;    // 32
static constexpr int NBLKS  = NCOL / 8;       // 256
static constexpr int GNBLKS = GCOL / 8;       // 4

// Tiling: 4 warps of 64x64 (min L1-port traffic per MMA)
static constexpr int BM     = 128;            // 8 m_blks -> 2048 CTAs
static constexpr int BN     = 128;            // 16 n_blks
static constexpr int KC     = 32;             // 4 k_blks / 2 k_blk2s
static constexpr int KSTEPS = IN_DIM / KC;    // 16
static constexpr int STAGES = 3;
static constexpr int NTHREADS = 128;          // 4 warps, 2(m) x 2(n), warp tile 64x64

// Shared memory (float4 units): stage = A(8*4*32) + B(16*2*32) = 2048 f4 = 32KB
static constexpr int A_STAGE_F4 = 8 * 4 * 32;     // 1024
static constexpr int B_STAGE_F4 = 16 * 2 * 32;    // 1024
static constexpr int STAGE_F4   = A_STAGE_F4 + B_STAGE_F4;  // 2048
static constexpr int HDR_F4     = 32;             // be slice (128 floats)
static constexpr int SMEM_F4    = HDR_F4 + STAGES * STAGE_F4;
static constexpr int SMEM_BYTES = SMEM_F4 * 16;   // 98816 (x2 CTA = 193 KB)
static constexpr int C_LD       = BN + 4;         // 132 (staging 128*132*4 = 67.6 KB)

// ============================================================================
// Device scratch (no allocations allowed)
// ============================================================================
__device__ float  g_gates[BATCH * GCOL];                  // softmaxed gates [b][e*4+t]
__device__ float4 g_xA  [(size_t)MBLKS * KBLKS * 32];     // A fragments (32 MB)
__device__ float4 g_WeB [(size_t)NBLKS * KBLK2S * 32];    // We B fragments (4 MB)
__device__ float4 g_WgB [(size_t)GNBLKS * KBLK2S * 32];   // Wg B fragments (64 KB)

// ============================================================================
// Helpers
// ============================================================================
__device__ __forceinline__ uint32_t smem_u32(const void* p) {
    uint32_t a;
    asm("{ .reg .u64 t; cvta.to.shared.u64 t, %1; cvt.u32.u64 %0, t; }" : "=r"(a) : "l"(p));
    return a;
}
__device__ __forceinline__ float tf32_rn(float f) {
    uint32_t o; asm("cvt.rn.tf32.f32 %0, %1;" : "=r"(o) : "f"(f));
    return __uint_as_float(o);
}
__device__ __forceinline__ void cp_async16(uint32_t dst, const void* src) {
    asm volatile("cp.async.cg.shared.global [%0], [%1], 16;\n" :: "r"(dst), "l"(src));
}
#define CP_COMMIT()       asm volatile("cp.async.commit_group;\n" ::: "memory")
#define CP_WAIT_GROUP_1() asm volatile("cp.async.wait_group 1;\n" ::: "memory")

// D += A(16x8) * B(8x8), tf32 operands, f32 accum
__device__ __forceinline__ void mma_tf32(float* c, const float4& a, float b0, float b1) {
    asm volatile(
        "mma.sync.aligned.m16n8k8.row.col.f32.tf32.tf32.f32 "
        "{%0,%1,%2,%3}, {%4,%5,%6,%7}, {%8,%9}, {%0,%1,%2,%3};"
        : "+f"(c[0]), "+f"(c[1]), "+f"(c[2]), "+f"(c[3])
        : "r"(__float_as_uint(a.x)), "r"(__float_as_uint(a.y)),
          "r"(__float_as_uint(a.z)), "r"(__float_as_uint(a.w)),
          "r"(__float_as_uint(b0)),  "r"(__float_as_uint(b1)));
}

// ============================================================================
// prep: We pack (blocks 0..255) + Wg pack (block 256), tf32-rounded B-frags
// ============================================================================
__global__ void __launch_bounds__(256)
prep_W_kernel(const float* __restrict__ We, const float* __restrict__ Wg) {
    const int t = threadIdx.x;
    if (blockIdx.x < NBLKS) {
        const int n_blk = blockIdx.x;
        #pragma unroll
        for (int i = 0; i < 4; i++) {
            int slot = t + i * 256;            // 1024 slots = 32 k2 x 32 lanes
            int k2   = slot >> 5;
            int lane = slot & 31;
            int gr = lane >> 2, tig = lane & 3;
            int n  = n_blk * 8 + gr;
            int kb = k2 * 16;
            float4 v;
            v.x = tf32_rn(__ldg(We + (size_t)(kb + tig)      * NCOL + n));
            v.y = tf32_rn(__ldg(We + (size_t)(kb + tig + 4)  * NCOL + n));
            v.z = tf32_rn(__ldg(We + (size_t)(kb + 8 + tig)  * NCOL + n));
            v.w = tf32_rn(__ldg(We + (size_t)(kb + 12 + tig) * NCOL + n));
            g_WeB[((size_t)n_blk * KBLK2S + k2) * 32 + lane] = v;
        }
    } else {
        // Wg pack: 4 gnblk x 32 k2 x 32 lanes = 4096 slots
        #pragma unroll
        for (int i = 0; i < 16; i++) {
            int slot = t + i * 256;
            int gn   = slot >> 10;
            int rem  = slot & 1023;
            int k2   = rem >> 5;
            int lane = rem & 31;
            int gr = lane >> 2, tig = lane & 3;
            int n  = gn * 8 + gr;
            int kb = k2 * 16;
            float4 v;
            v.x = tf32_rn(__ldg(Wg + (size_t)(kb + tig)      * GCOL + n));
            v.y = tf32_rn(__ldg(Wg + (size_t)(kb + tig + 4)  * GCOL + n));
            v.z = tf32_rn(__ldg(Wg + (size_t)(kb + 8 + tig)  * GCOL + n));
            v.w = tf32_rn(__ldg(Wg + (size_t)(kb + 12 + tig) * GCOL + n));
            g_WgB[slot] = v;   // (gn*32 + k2)*32 + lane == slot
        }
    }
}

// ============================================================================
// Gate kernel: x tf32-round + A-fragment pack + TENSOR-CORE gate logits
//              + softmax. One block = 16 rows = one m_blk.
// ============================================================================
static constexpr int XS_LD = IN_DIM + 4;   // 516 (conflict-free pack reads)

__global__ void __launch_bounds__(512)
gate_kernel(const float4* __restrict__ x4, const float* __restrict__ bg) {
    __shared__ float xs[16][XS_LD];        // 33 KB
    __shared__ float ls[16][GCOL];         //  2 KB
    const int tid  = threadIdx.x;
    const int wid  = tid >> 5;
    const int lane = tid & 31;
    const int gr   = lane >> 2, tig = lane & 3;
    const int blk  = blockIdx.x;           // m_blk
    const int b0   = blk * 16;

    // load + tf32-round into smem
    #pragma unroll
    for (int i = 0; i < 4; i++) {
        int idx = tid + i * 512;           // float4 index within 16x512 tile
        int rr = idx >> 7, c = idx & 127;
        float4 v = x4[(size_t)(b0 + rr) * (IN_DIM / 4) + c];
        v.x = tf32_rn(v.x); v.y = tf32_rn(v.y); v.z = tf32_rn(v.z); v.w = tf32_rn(v.w);
        *(float4*)&xs[rr][c * 4] = v;
    }
    __syncthreads();

    // write A fragments to gmem (2048 slots = 64 k_blk x 32 lanes)
    #pragma unroll
    for (int i = 0; i < 4; i++) {
        int slot = tid + i * 512;
        int k_blk = slot >> 5;
        int ln    = slot & 31;
        int g2 = ln >> 2, t2 = ln & 3;
        int kc = k_blk * 8;
        float4 v;
        v.x = xs[g2][kc + t2];
        v.y = xs[g2 + 8][kc + t2];
        v.z = xs[g2][kc + t2 + 4];
        v.w = xs[g2 + 8][kc + t2 + 4];
        g_xA[((size_t)blk * KBLKS + k_blk) * 32 + ln] = v;
    }
    __syncthreads();   // global writes by this block now visible to this block

    // gate logits via tensor cores: warps 0..3, one gate n-blk each
    if (wid < GNBLKS) {
        float a[4] = {0.f, 0.f, 0.f, 0.f};
        const float4* WgB = g_WgB + (size_t)wid * KBLK2S * 32;
        const float4* xA  = g_xA + (size_t)blk * KBLKS * 32;
        #pragma unroll 4
        for (int k2 = 0; k2 < KBLK2S; k2++) {
            float4 Bv  = WgB[k2 * 32 + lane];
            float4 Av0 = xA[(k2 * 2) * 32 + lane];
            float4 Av1 = xA[(k2 * 2 + 1) * 32 + lane];
            mma_tf32(a, Av0, Bv.x, Bv.y);
            mma_tf32(a, Av1, Bv.z, Bv.w);
        }
        // C frag mapping: rows gr/gr+8, cols 2*tig/2*tig+1 within n-blk
        ls[gr][wid * 8 + 2 * tig]         = a[0];
        ls[gr][wid * 8 + 2 * tig + 1]     = a[1];
        ls[gr + 8][wid * 8 + 2 * tig]     = a[2];
        ls[gr + 8][wid * 8 + 2 * tig + 1] = a[3];
    }
    __syncthreads();

    // softmax over experts, per (row, task)
    if (tid < 64) {
        const int rr = tid >> 2, t = tid & 3;
        float v[NEXP], m = -3.4e38f;
        #pragma unroll
        for (int e = 0; e < NEXP; e++) {
            v[e] = ls[rr][e * 4 + t] + bg[e * 4 + t];
            m = fmaxf(m, v[e]);
        }
        float den = 0.f;
        #pragma unroll
        for (int e = 0; e < NEXP; e++) { v[e] = expf(v[e] - m); den += v[e]; }
        const float inv = 1.f / den;
        #pragma unroll
        for (int e = 0; e < NEXP; e++)
            g_gates[(size_t)(b0 + rr) * GCOL + e * 4 + t] = v[e] * inv;
    }
}

// ============================================================================
// Main kernel: mma.m16n8k8 tf32, 64x64 warp tiles (unchanged from r12)
// ============================================================================
__global__ void __launch_bounds__(NTHREADS, 2)
moe_mma_kernel(const float* __restrict__ be, float* __restrict__ out) {
    extern __shared__ float4 smem4[];
    float*  sbe    = (float*)smem4;
    float4* stage0 = smem4 + HDR_F4;

    const int tid  = threadIdx.x;
    const int wid  = tid >> 5;
    const int lane = tid & 31;
    const int gr   = lane >> 2, tig = lane & 3;
    const int warp_m = wid >> 1;        // 0..1 -> rows warp_m*64
    const int warp_n = wid & 1;         // 0..1 -> cols warp_n*64

    const int n_tile = blockIdx.x & 15;
    const int b_tile = blockIdx.x >> 4;
    const int b0  = b_tile * BM;
    const int mb0 = b_tile * 8;         // global m_blk base
    const int nb0 = n_tile * 16;        // global n_blk base

    if (tid < BN) sbe[tid] = be[n_tile * BN + tid];

    float acc[4][8][4];                 // [mi][ni][frag] = 128 regs
    #pragma unroll
    for (int mi = 0; mi < 4; mi++)
        #pragma unroll
        for (int ni = 0; ni < 8; ni++)
            #pragma unroll
            for (int q = 0; q < 4; q++) acc[mi][ni][q] = 0.f;

    auto load_stage = [&](int slot, int kt) {
        float4* As = stage0 + slot * STAGE_F4;
        float4* Bs = As + A_STAGE_F4;
        const uint32_t aB = smem_u32(As);
        const uint32_t bB = smem_u32(Bs);
        // A: 1024 chunks -> 8 per thread
        #pragma unroll
        for (int i = 0; i < 8; i++) {
            int c = tid + i * 128;
            int mb = c >> 7, rem = c & 127;
            size_t g = ((size_t)(mb0 + mb) * KBLKS + (kt * 4 + (rem >> 5))) * 32 + (rem & 31);
            cp_async16(aB + (uint32_t)c * 16, g_xA + g);
        }
        // B: 1024 chunks -> 8 per thread
        #pragma unroll
        for (int i = 0; i < 8; i++) {
            int c = tid + i * 128;
            int nb = c >> 6, rem = c & 63;
            size_t g = ((size_t)(nb0 + nb) * KBLK2S + (kt * 2 + (rem >> 5))) * 32 + (rem & 31);
            cp_async16(bB + (uint32_t)c * 16, g_WeB + g);
        }
    };

    auto compute_stage = [&](int slot) {
        const float4* As = stage0 + slot * STAGE_F4;
        const float4* Bs = As + A_STAGE_F4;
        #pragma unroll
        for (int k2 = 0; k2 < 2; k2++) {
            float4 Bv[8];
            #pragma unroll
            for (int ni = 0; ni < 8; ni++)
                Bv[ni] = Bs[((warp_n * 8 + ni) * 2 + k2) * 32 + lane];
            #pragma unroll
            for (int half = 0; half < 2; half++) {
                const int ks = k2 * 2 + half;
                float4 Av[4];
                #pragma unroll
                for (int mi = 0; mi < 4; mi++)
                    Av[mi] = As[((warp_m * 4 + mi) * 4 + ks) * 32 + lane];
                #pragma unroll
                for (int mi = 0; mi < 4; mi++)
                    #pragma unroll
                    for (int ni = 0; ni < 8; ni++) {
                        if (half == 0) mma_tf32(acc[mi][ni], Av[mi], Bv[ni].x, Bv[ni].y);
                        else           mma_tf32(acc[mi][ni], Av[mi], Bv[ni].z, Bv[ni].w);
                    }
            }
        }
    };

    // Prologue: fill 2 of 3 stages
    load_stage(0, 0); CP_COMMIT();
    load_stage(1, 1); CP_COMMIT();

    // Main loop
    for (int kt = 0; kt < KSTEPS; kt++) {
        CP_WAIT_GROUP_1();
        __syncthreads();
        const int next = kt + 2;
        if (next < KSTEPS) load_stage(next % STAGES, next);
        CP_COMMIT();
        compute_stage(kt % STAGES);
    }

    // ------------------------------------------------------------------
    // Epilogue: stage C through smem, then bias+ReLU+gate combine
    // ------------------------------------------------------------------
    __syncthreads();
    float* Cs = (float*)stage0;   // 128 x 132 floats = 67.6 KB
    #pragma unroll
    for (int mi = 0; mi < 4; mi++) {
        #pragma unroll
        for (int ni = 0; ni < 8; ni++) {
            int row = warp_m * 64 + mi * 16 + gr;
            int col = warp_n * 64 + ni * 8 + 2 * tig;
            *(float2*)&Cs[row * C_LD + col]       = make_float2(acc[mi][ni][0], acc[mi][ni][1]);
            *(float2*)&Cs[(row + 8) * C_LD + col] = make_float2(acc[mi][ni][2], acc[mi][ni][3]);
        }
    }
    __syncthreads();

    const int r = tid;            // row in tile (0..127), one row per thread
    const int b = b0 + r;

    float gate[GCOL];
    {
        const float4* gp = (const float4*)(g_gates + (size_t)b * GCOL);
        #pragma unroll
        for (int q = 0; q < 8; q++) ((float4*)gate)[q] = gp[q];
    }

    float accu[16][NTASK];
    #pragma unroll
    for (int u = 0; u < 16; u++)
        #pragma unroll
        for (int t = 0; t < NTASK; t++) accu[u][t] = 0.f;

    #pragma unroll
    for (int u = 0; u < 16; u++) {
        const int nl = u * 8;
        #pragma unroll
        for (int e = 0; e < NEXP; e++) {
            float v = Cs[r * C_LD + nl + e] + sbe[nl + e];
            v = fmaxf(v, 0.f);
            #pragma unroll
            for (int t = 0; t < NTASK; t++) accu[u][t] += v * gate[e * 4 + t];
        }
    }

    float* ob = out + (size_t)b * UNITS + n_tile * 16;
    #pragma unroll
    for (int t = 0; t < NTASK; t++) {
        #pragma unroll
        for (int q = 0; q < 4; q++) {
            float4 o = make_float4(accu[q * 4 + 0][t], accu[q * 4 + 1][t],
                                   accu[q * 4 + 2][t], accu[q * 4 + 3][t]);
            *(float4*)(ob + (size_t)t * BATCH * UNITS + q * 4) = o;
        }
    }
}

// ============================================================================
// Launch
// ============================================================================
extern "C" void kernel_launch(void* const* d_in, const int* in_sizes, int n_in,
                              void* d_out, int out_size) {
    const float* x  = (const float*)d_in[0];
    const float* We = (const float*)d_in[1];
    const float* be = (const float*)d_in[2];
    const float* Wg = (const float*)d_in[3];
    const float* bg = (const float*)d_in[4];
    float* out = (float*)d_out;

    cudaFuncSetAttribute(moe_mma_kernel, cudaFuncAttributeMaxDynamicSharedMemorySize, SMEM_BYTES);

    prep_W_kernel<<<NBLKS + 1, 256>>>(We, Wg);
    gate_kernel<<<MBLKS, 512>>>((const float4*)x, bg);
    moe_mma_kernel<<<(BATCH / BM) * (NCOL / BN), NTHREADS, SMEM_BYTES>>>(be, out);
}